// round 8
// baseline (speedup 1.0000x reference)
#include <cuda_runtime.h>
#include <cuda_bf16.h>
#include <math.h>

// Problem constants
#define Bc   1024
#define Lc   8
#define Ec   256
#define Rc   10000
#define RP1  10001
#define G4   1024       // 4*E
#define ECC  512        // 2*E

// GEMM flags
#define FLAG_ACC   1
#define FLAG_RELU  2
#define FLAG_GBIAS 4

// GEMM op selectors (pick internal device-global operands)
#define OP_GATES_X 0
#define OP_GATES_H 1
#define OP_FC1     2
#define OP_FC2     3

// ---------------- scratch (device globals; no runtime allocation) ----------------
__device__ float g_x   [Bc * Lc * Ec];   // embedded inputs
__device__ float g_h   [Bc * Ec];        // LSTM hidden
__device__ float g_c   [Bc * Ec];        // LSTM cell
__device__ float g_gates[Bc * G4];       // LSTM gate pre-activations
__device__ float g_hid [Bc * Lc * Ec];   // body_hid
__device__ float g_ec  [Bc * ECC];       // emb_concat
__device__ float g_h1  [Bc * Ec];        // fc1 output
__device__ float g_sf  [Bc * RP1];       // softmax(prob)
__device__ float g_part[4 * Bc * Ec];    // split-K partials for NN gemm
__device__ float g_bias[G4];             // b_ih + b_hh

// ---------------- small kernels ----------------
__global__ void k_embed(const int* __restrict__ bodys, const float* __restrict__ emb_w) {
    int idx = blockIdx.x * 256 + threadIdx.x;            // over B*L*E
    if (idx < Bc * Lc * Ec) {
        int e  = idx & (Ec - 1);
        int bl = idx >> 8;
        g_x[idx] = emb_w[bodys[bl] * Ec + e];
    }
}

__global__ void k_init(const float* __restrict__ b_ih, const float* __restrict__ b_hh) {
    int idx = blockIdx.x * 256 + threadIdx.x;            // over B*E
    if (idx < G4) g_bias[idx] = b_ih[idx] + b_hh[idx];
    if (idx < Bc * Ec) { g_h[idx] = 0.f; g_c[idx] = 0.f; }
}

__global__ void k_lstm_point(int t) {
    int idx = blockIdx.x * 256 + threadIdx.x;            // over B*E
    if (idx >= Bc * Ec) return;
    int b = idx >> 8, j = idx & (Ec - 1);
    const float* g = &g_gates[b * G4];
    float ig = 1.f / (1.f + __expf(-g[j]));
    float fg = 1.f / (1.f + __expf(-g[j + Ec]));
    float gg = tanhf(g[j + 2 * Ec]);
    float og = 1.f / (1.f + __expf(-g[j + 3 * Ec]));
    float c  = fg * g_c[idx] + ig * gg;
    float h  = og * tanhf(c);
    g_c[idx] = c;
    g_h[idx] = h;
    g_hid[(b * Lc + t) * Ec + j] = h;
}

__global__ void k_ec0() {
    int idx = blockIdx.x * 256 + threadIdx.x;            // over B*E
    if (idx >= Bc * Ec) return;
    int b = idx >> 8, e = idx & (Ec - 1);
    g_ec[b * ECC + e]      = g_x[(b * Lc + 0) * Ec + e];
    g_ec[b * ECC + Ec + e] = g_x[(b * Lc + 1) * Ec + e];
}

__global__ void k_ec_second(const float* __restrict__ emb_w, int i) {
    int idx = blockIdx.x * 256 + threadIdx.x;            // over B*E
    if (idx >= Bc * Ec) return;
    int b = idx >> 8, e = idx & (Ec - 1);
    g_ec[b * ECC + Ec + e] = emb_w[(i + 1) * Ec + e];
}

__global__ void k_nn_reduce(int i) {
    int idx = blockIdx.x * 256 + threadIdx.x;            // over B*E
    if (idx >= Bc * Ec) return;
    int b = idx >> 8, e = idx & (Ec - 1);
    float v = g_part[idx] + g_part[Bc * Ec + idx]
            + g_part[2 * Bc * Ec + idx] + g_part[3 * Bc * Ec + idx];
    v += g_sf[b * RP1 + Rc] * g_hid[(b * Lc + i) * Ec + e];
    g_ec[b * ECC + e] = v;
}

__global__ void k_copy_ec(float* __restrict__ out, int out_size) {
    int idx = blockIdx.x * 256 + threadIdx.x;            // over B*2E
    if (idx >= Bc * ECC) return;
    int dst = Bc * RP1 + idx;
    if (dst < out_size) out[dst] = g_ec[idx];
}

// ---------------- generic NT GEMM: C[m,n] = sum_k A[m,k]*W[n,k] (+epilogue) ----
// M fixed at gridDim.y*64 (=1024 here). BM=BN=64, BK=16, 256 thr, 4x4 micro.
__global__ void __launch_bounds__(256)
k_gemm_nt(int op, int t, const float* __restrict__ W,
          const float* __restrict__ bias, float* __restrict__ outC,
          int N, int K)
{
    const float* A; int lda; float* C; int ldc; int flags;
    switch (op) {
        default:
        case OP_GATES_X: A = g_x + t * Ec; lda = Lc * Ec; C = g_gates; ldc = G4;
                         flags = FLAG_GBIAS; break;
        case OP_GATES_H: A = g_h;  lda = Ec;  C = g_gates; ldc = G4;
                         flags = FLAG_ACC;   break;
        case OP_FC1:     A = g_ec; lda = ECC; C = g_h1;    ldc = Ec;
                         flags = FLAG_RELU;  break;
        case OP_FC2:     A = g_h1; lda = Ec;  C = outC;    ldc = RP1;
                         flags = 0;          break;
    }
    const int ldb = K;   // all W operands here have row stride == K

    __shared__ float As[16][64];
    __shared__ float Bs[16][64];

    int tid = threadIdx.x;
    int tx = tid & 15, ty = tid >> 4;
    int m0 = blockIdx.y * 64, n0 = blockIdx.x * 64;

    int lm = tid >> 2;          // 0..63 (tile row)
    int lk = (tid & 3) * 4;     // 0,4,8,12

    float acc[4][4] = {};

    for (int k0 = 0; k0 < K; k0 += 16) {
        float4 av = *(const float4*)&A[(m0 + lm) * lda + k0 + lk];
        As[lk + 0][lm] = av.x; As[lk + 1][lm] = av.y;
        As[lk + 2][lm] = av.z; As[lk + 3][lm] = av.w;

        int bn = n0 + lm;
        float4 bv = make_float4(0.f, 0.f, 0.f, 0.f);
        if (bn < N) bv = *(const float4*)&W[bn * ldb + k0 + lk];
        Bs[lk + 0][lm] = bv.x; Bs[lk + 1][lm] = bv.y;
        Bs[lk + 2][lm] = bv.z; Bs[lk + 3][lm] = bv.w;
        __syncthreads();

        #pragma unroll
        for (int kk = 0; kk < 16; kk++) {
            float a[4], b[4];
            *(float4*)a = *(const float4*)&As[kk][ty * 4];
            *(float4*)b = *(const float4*)&Bs[kk][tx * 4];
            #pragma unroll
            for (int i = 0; i < 4; i++)
                #pragma unroll
                for (int j = 0; j < 4; j++)
                    acc[i][j] = fmaf(a[i], b[j], acc[i][j]);
        }
        __syncthreads();
    }

    #pragma unroll
    for (int i = 0; i < 4; i++) {
        int m = m0 + ty * 4 + i;
        #pragma unroll
        for (int j = 0; j < 4; j++) {
            int n = n0 + tx * 4 + j;
            if (n < N) {
                float v = acc[i][j];
                if (flags & FLAG_ACC)   v += C[m * ldc + n];
                if (bias)               v += bias[n];
                if (flags & FLAG_GBIAS) v += g_bias[n];
                if (flags & FLAG_RELU)  v = fmaxf(v, 0.f);
                C[m * ldc + n] = v;
            }
        }
    }
}

// ---------------- NN split-K GEMM: part[s][m,n] = sum_{k in split s} sf[m,k]*emb_w[k,n]
// M=1024, N=256, K=10000, split-K=4 (deterministic, no atomics).
__global__ void __launch_bounds__(256)
k_gemm_nn_sk(const float* __restrict__ emb_w)
{
    __shared__ float As[16][64];
    __shared__ float Bs[16][64];

    int tid = threadIdx.x;
    int tx = tid & 15, ty = tid >> 4;
    int n0 = blockIdx.x * 64, m0 = blockIdx.y * 64, sid = blockIdx.z;

    const int KT = Rc / 16;            // 625 k-tiles
    int kt0 = sid * 157;
    int kt1 = min(KT, kt0 + 157);

    int lmA = tid >> 2;                // 0..63
    int lkA = (tid & 3) * 4;
    int lkB = tid >> 4;                // 0..15
    int lnB = (tid & 15) * 4;

    float acc[4][4] = {};

    for (int kt = kt0; kt < kt1; kt++) {
        int k0 = kt * 16;
        const float* ap = &g_sf[(m0 + lmA) * RP1 + k0 + lkA];  // odd stride: scalar
        As[lkA + 0][lmA] = ap[0];
        As[lkA + 1][lmA] = ap[1];
        As[lkA + 2][lmA] = ap[2];
        As[lkA + 3][lmA] = ap[3];
        *(float4*)&Bs[lkB][lnB] = *(const float4*)&emb_w[(k0 + lkB) * Ec + n0 + lnB];
        __syncthreads();

        #pragma unroll
        for (int kk = 0; kk < 16; kk++) {
            float a[4], b[4];
            *(float4*)a = *(const float4*)&As[kk][ty * 4];
            *(float4*)b = *(const float4*)&Bs[kk][tx * 4];
            #pragma unroll
            for (int i = 0; i < 4; i++)
                #pragma unroll
                for (int j = 0; j < 4; j++)
                    acc[i][j] = fmaf(a[i], b[j], acc[i][j]);
        }
        __syncthreads();
    }

    float* P = &g_part[sid * (Bc * Ec)];
    #pragma unroll
    for (int i = 0; i < 4; i++)
        #pragma unroll
        for (int j = 0; j < 4; j++)
            P[(m0 + ty * 4 + i) * Ec + n0 + tx * 4 + j] = acc[i][j];
}

// ---------------- softmax over RP1 per row (block/row, smem-cached) ----------
__global__ void __launch_bounds__(256)
k_softmax(const float* __restrict__ in)
{
    __shared__ float buf[RP1];
    __shared__ float red[256];
    int row = blockIdx.x, tid = threadIdx.x;
    const float* x = in + row * RP1;

    float mx = -1e30f;
    for (int j = tid; j < RP1; j += 256) {
        float v = x[j];
        buf[j] = v;
        mx = fmaxf(mx, v);
    }
    red[tid] = mx;
    __syncthreads();
    for (int s = 128; s > 0; s >>= 1) {
        if (tid < s) red[tid] = fmaxf(red[tid], red[tid + s]);
        __syncthreads();
    }
    mx = red[0];
    __syncthreads();

    float sm = 0.f;
    for (int j = tid; j < RP1; j += 256) {
        float e = __expf(buf[j] - mx);
        buf[j] = e;
        sm += e;
    }
    red[tid] = sm;
    __syncthreads();
    for (int s = 128; s > 0; s >>= 1) {
        if (tid < s) red[tid] += red[tid + s];
        __syncthreads();
    }
    float inv = 1.f / red[0];
    for (int j = tid; j < RP1; j += 256)
        g_sf[row * RP1 + j] = buf[j] * inv;
}

// ---------------- launch sequence ----------------
extern "C" void kernel_launch(void* const* d_in, const int* in_sizes, int n_in,
                              void* d_out, int out_size)
{
    const int*   bodys = (const int*)  d_in[0];
    const float* emb_w = (const float*)d_in[1];
    const float* w_ih  = (const float*)d_in[2];
    const float* w_hh  = (const float*)d_in[3];
    const float* b_ih  = (const float*)d_in[4];
    const float* b_hh  = (const float*)d_in[5];
    const float* fc1_w = (const float*)d_in[6];
    const float* fc1_b = (const float*)d_in[7];
    const float* fc2_w = (const float*)d_in[8];
    const float* fc2_b = (const float*)d_in[9];
    float* out = (float*)d_out;

    // Embed + init
    k_embed<<<(Bc * Lc * Ec) / 256, 256>>>(bodys, emb_w);
    k_init<<<(Bc * Ec) / 256, 256>>>(b_ih, b_hh);

    // LSTM: steps 0..6 only (step 7's hidden state is never consumed)
    for (int t = 0; t < Lc - 1; t++) {
        k_gemm_nt<<<dim3(16, 16), 256>>>(OP_GATES_X, t, w_ih, nullptr, nullptr, G4, Ec);
        k_gemm_nt<<<dim3(16, 16), 256>>>(OP_GATES_H, 0, w_hh, nullptr, nullptr, G4, Ec);
        k_lstm_point<<<(Bc * Ec) / 256, 256>>>(t);
    }

    // Autoregressive loop
    for (int i = 0; i < Lc - 1; i++) {
        if (i == 0) {
            k_ec0<<<(Bc * Ec) / 256, 256>>>();
        } else {
            k_gemm_nn_sk<<<dim3(Ec / 64, Bc / 64, 4), 256>>>(emb_w);
            k_nn_reduce<<<(Bc * Ec) / 256, 256>>>(i);
            k_ec_second<<<(Bc * Ec) / 256, 256>>>(emb_w, i);
        }
        // fc1: (B,512)@(512->256), relu+bias
        k_gemm_nt<<<dim3(Ec / 64, Bc / 64), 256>>>(OP_FC1, 0, fc1_w, fc1_b, nullptr, Ec, ECC);
        // fc2: (B,256)@(256->10001), bias, write directly into d_out (final iter persists)
        k_gemm_nt<<<dim3((RP1 + 63) / 64, Bc / 64), 256>>>(OP_FC2, 0, fc2_w, fc2_b, out, RP1, Ec);
        // softmax feeds the NEXT iteration; skip on the last one
        if (i < Lc - 2) k_softmax<<<Bc, 256>>>(out);
    }

    // emb_concat (final) appended after prob in d_out
    k_copy_ec<<<(Bc * ECC) / 256, 256>>>(out, out_size);
}

// round 10
// speedup vs baseline: 1.0964x; 1.0964x over previous
#include <cuda_runtime.h>
#include <cuda_bf16.h>
#include <math.h>

// Problem constants
#define Bc   1024
#define Lc   8
#define Ec   256
#define Rc   10000
#define RP1  10001
#define G4   1024       // 4*E
#define ECC  512        // 2*E

// big-tile GEMM config
#define BM 128
#define BN 128
#define BK 8
#define PAD 132         // smem row pad (132*4B = 528B, 16B aligned, kills STS conflicts)
#define NSPLIT 16       // split-K for the NN gemm

// ---------------- scratch (device globals; no runtime allocation) ----------------
__device__ float g_x   [Bc * Lc * Ec];   // embedded inputs
__device__ float g_h   [Bc * Ec];        // LSTM hidden
__device__ float g_c   [Bc * Ec];        // LSTM cell
__device__ float g_gates[Bc * G4];       // LSTM gate pre-activations
__device__ float g_hid [Bc * Lc * Ec];   // body_hid
__device__ float g_ec  [Bc * ECC];       // emb_concat
__device__ float g_h1  [Bc * Ec];        // fc1 output
__device__ float g_sf  [Bc * RP1];       // softmax(prob)
__device__ float g_part[NSPLIT * Bc * Ec]; // split-K partials for NN gemm
__device__ float g_bias[G4];             // b_ih + b_hh

// ---------------- small kernels ----------------
__global__ void k_embed(const int* __restrict__ bodys, const float* __restrict__ emb_w) {
    int idx = blockIdx.x * 256 + threadIdx.x;            // over B*L*E
    if (idx < Bc * Lc * Ec) {
        int e  = idx & (Ec - 1);
        int bl = idx >> 8;
        g_x[idx] = emb_w[bodys[bl] * Ec + e];
    }
}

__global__ void k_init(const float* __restrict__ b_ih, const float* __restrict__ b_hh) {
    int idx = blockIdx.x * 256 + threadIdx.x;            // over B*E
    if (idx < G4) g_bias[idx] = b_ih[idx] + b_hh[idx];
    if (idx < Bc * Ec) { g_h[idx] = 0.f; g_c[idx] = 0.f; }
}

__global__ void k_lstm_point(int t) {
    int idx = blockIdx.x * 256 + threadIdx.x;            // over B*E
    if (idx >= Bc * Ec) return;
    int b = idx >> 8, j = idx & (Ec - 1);
    const float* g = &g_gates[b * G4];
    float ig = 1.f / (1.f + __expf(-g[j]));
    float fg = 1.f / (1.f + __expf(-g[j + Ec]));
    float gg = tanhf(g[j + 2 * Ec]);
    float og = 1.f / (1.f + __expf(-g[j + 3 * Ec]));
    float c  = fg * g_c[idx] + ig * gg;
    float h  = og * tanhf(c);
    g_c[idx] = c;
    g_h[idx] = h;
    g_hid[(b * Lc + t) * Ec + j] = h;
}

__global__ void k_ec0() {
    int idx = blockIdx.x * 256 + threadIdx.x;            // over B*E
    if (idx >= Bc * Ec) return;
    int b = idx >> 8, e = idx & (Ec - 1);
    g_ec[b * ECC + e]      = g_x[(b * Lc + 0) * Ec + e];
    g_ec[b * ECC + Ec + e] = g_x[(b * Lc + 1) * Ec + e];
}

__global__ void k_ec_second(const float* __restrict__ emb_w, int i) {
    int idx = blockIdx.x * 256 + threadIdx.x;            // over B*E
    if (idx >= Bc * Ec) return;
    int b = idx >> 8, e = idx & (Ec - 1);
    g_ec[b * ECC + Ec + e] = emb_w[(i + 1) * Ec + e];
}

__global__ void k_nn_reduce(int i) {
    int idx = blockIdx.x * 256 + threadIdx.x;            // over B*E
    if (idx >= Bc * Ec) return;
    int b = idx >> 8, e = idx & (Ec - 1);
    float v = 0.f;
    #pragma unroll
    for (int s = 0; s < NSPLIT; s++) v += g_part[s * (Bc * Ec) + idx];
    v += g_sf[b * RP1 + Rc] * g_hid[(b * Lc + i) * Ec + e];
    g_ec[b * ECC + e] = v;
}

__global__ void k_copy_ec(float* __restrict__ out, int out_size) {
    int idx = blockIdx.x * 256 + threadIdx.x;            // over B*2E
    if (idx >= Bc * ECC) return;
    int dst = Bc * RP1 + idx;
    if (dst < out_size) out[dst] = g_ec[idx];
}

// ============ 128x128x8 double-buffered NT GEMM core (8x8 micro-tile) ============
// fc2: C[m,n] = sum_k g_h1[m,k] * W[n,k] + bias[n], N = RP1 (edge-guarded)
__global__ void __launch_bounds__(256)
k_fc2(const float* __restrict__ W, const float* __restrict__ bias,
      float* __restrict__ out)
{
    __shared__ float As[2][BK][PAD];
    __shared__ float Bs[2][BK][PAD];

    int tid  = threadIdx.x;
    int m0   = blockIdx.y * BM, n0 = blockIdx.x * BN;
    int arow = tid >> 1;                // 0..127
    int ac4  = (tid & 1) * 4;           // 0 or 4
    int bn   = n0 + arow;
    int tx   = tid & 15, ty = tid >> 4;

    const float* A = g_h1;              // lda = Ec
    const int NK = Ec / BK;             // 32

    float4 pa = *(const float4*)&A[(m0 + arow) * Ec + ac4];
    float4 pb = (bn < RP1) ? *(const float4*)&W[bn * Ec + ac4]
                           : make_float4(0.f, 0.f, 0.f, 0.f);
    As[0][ac4 + 0][arow] = pa.x; As[0][ac4 + 1][arow] = pa.y;
    As[0][ac4 + 2][arow] = pa.z; As[0][ac4 + 3][arow] = pa.w;
    Bs[0][ac4 + 0][arow] = pb.x; Bs[0][ac4 + 1][arow] = pb.y;
    Bs[0][ac4 + 2][arow] = pb.z; Bs[0][ac4 + 3][arow] = pb.w;
    __syncthreads();

    float acc[8][8] = {};
    int buf = 0;
    for (int kt = 0; kt < NK; kt++) {
        if (kt + 1 < NK) {
            int k0 = (kt + 1) * BK;
            pa = *(const float4*)&A[(m0 + arow) * Ec + k0 + ac4];
            pb = (bn < RP1) ? *(const float4*)&W[bn * Ec + k0 + ac4]
                            : make_float4(0.f, 0.f, 0.f, 0.f);
        }
        #pragma unroll
        for (int kk = 0; kk < BK; kk++) {
            float a[8], b[8];
            *(float4*)&a[0] = *(const float4*)&As[buf][kk][ty * 8];
            *(float4*)&a[4] = *(const float4*)&As[buf][kk][ty * 8 + 4];
            *(float4*)&b[0] = *(const float4*)&Bs[buf][kk][tx * 8];
            *(float4*)&b[4] = *(const float4*)&Bs[buf][kk][tx * 8 + 4];
            #pragma unroll
            for (int i = 0; i < 8; i++)
                #pragma unroll
                for (int j = 0; j < 8; j++)
                    acc[i][j] = fmaf(a[i], b[j], acc[i][j]);
        }
        if (kt + 1 < NK) {
            int nb = buf ^ 1;
            As[nb][ac4 + 0][arow] = pa.x; As[nb][ac4 + 1][arow] = pa.y;
            As[nb][ac4 + 2][arow] = pa.z; As[nb][ac4 + 3][arow] = pa.w;
            Bs[nb][ac4 + 0][arow] = pb.x; Bs[nb][ac4 + 1][arow] = pb.y;
            Bs[nb][ac4 + 2][arow] = pb.z; Bs[nb][ac4 + 3][arow] = pb.w;
        }
        __syncthreads();
        buf ^= 1;
    }

    #pragma unroll
    for (int i = 0; i < 8; i++) {
        int m = m0 + ty * 8 + i;
        #pragma unroll
        for (int j = 0; j < 8; j++) {
            int n = n0 + tx * 8 + j;
            if (n < RP1) out[m * RP1 + n] = acc[i][j] + bias[n];
        }
    }
}

// Fused LSTM gates: g_gates = x_t @ w_ih^T + h @ w_hh^T + g_bias
// K = 512 over two segments (seg0: x_t/w_ih, seg1: h/w_hh). M=1024, N=1024.
__global__ void __launch_bounds__(256)
k_gates(int t, const float* __restrict__ w_ih, const float* __restrict__ w_hh)
{
    __shared__ float As[2][BK][PAD];
    __shared__ float Bs[2][BK][PAD];

    int tid  = threadIdx.x;
    int m0   = blockIdx.y * BM, n0 = blockIdx.x * BN;
    int arow = tid >> 1;
    int ac4  = (tid & 1) * 4;
    int tx   = tid & 15, ty = tid >> 4;

    const int NK = (2 * Ec) / BK;       // 64 (32 per segment)

    // fetch tile kt: segment resolved from kt
    auto fetch = [&](int kt, float4& pa, float4& pb) {
        if (kt < 32) {
            int k0 = kt * BK;
            pa = *(const float4*)&g_x[(m0 + arow) * (Lc * Ec) + t * Ec + k0 + ac4];
            pb = *(const float4*)&w_ih[(n0 + arow) * Ec + k0 + ac4];
        } else {
            int k0 = (kt - 32) * BK;
            pa = *(const float4*)&g_h[(m0 + arow) * Ec + k0 + ac4];
            pb = *(const float4*)&w_hh[(n0 + arow) * Ec + k0 + ac4];
        }
    };

    float4 pa, pb;
    fetch(0, pa, pb);
    As[0][ac4 + 0][arow] = pa.x; As[0][ac4 + 1][arow] = pa.y;
    As[0][ac4 + 2][arow] = pa.z; As[0][ac4 + 3][arow] = pa.w;
    Bs[0][ac4 + 0][arow] = pb.x; Bs[0][ac4 + 1][arow] = pb.y;
    Bs[0][ac4 + 2][arow] = pb.z; Bs[0][ac4 + 3][arow] = pb.w;
    __syncthreads();

    float acc[8][8] = {};
    int buf = 0;
    for (int kt = 0; kt < NK; kt++) {
        if (kt + 1 < NK) fetch(kt + 1, pa, pb);
        #pragma unroll
        for (int kk = 0; kk < BK; kk++) {
            float a[8], b[8];
            *(float4*)&a[0] = *(const float4*)&As[buf][kk][ty * 8];
            *(float4*)&a[4] = *(const float4*)&As[buf][kk][ty * 8 + 4];
            *(float4*)&b[0] = *(const float4*)&Bs[buf][kk][tx * 8];
            *(float4*)&b[4] = *(const float4*)&Bs[buf][kk][tx * 8 + 4];
            #pragma unroll
            for (int i = 0; i < 8; i++)
                #pragma unroll
                for (int j = 0; j < 8; j++)
                    acc[i][j] = fmaf(a[i], b[j], acc[i][j]);
        }
        if (kt + 1 < NK) {
            int nb = buf ^ 1;
            As[nb][ac4 + 0][arow] = pa.x; As[nb][ac4 + 1][arow] = pa.y;
            As[nb][ac4 + 2][arow] = pa.z; As[nb][ac4 + 3][arow] = pa.w;
            Bs[nb][ac4 + 0][arow] = pb.x; Bs[nb][ac4 + 1][arow] = pb.y;
            Bs[nb][ac4 + 2][arow] = pb.z; Bs[nb][ac4 + 3][arow] = pb.w;
        }
        __syncthreads();
        buf ^= 1;
    }

    #pragma unroll
    for (int i = 0; i < 8; i++) {
        int m = m0 + ty * 8 + i;
        #pragma unroll
        for (int j = 0; j < 8; j++) {
            int n = n0 + tx * 8 + j;
            g_gates[m * G4 + n] = acc[i][j] + g_bias[n];
        }
    }
}

// NN split-K GEMM, 128x128x8 tiles: part[s][m,n] = sum_{k in split s} sf[m,k]*emb_w[k,n]
// M=1024, N=256, K=10000. A rows have odd stride RP1 -> scalar A loads.
__global__ void __launch_bounds__(256)
k_nn(const float* __restrict__ emb_w)
{
    __shared__ float As[2][BK][PAD];
    __shared__ float Bs[2][BK][PAD];

    int tid  = threadIdx.x;
    int n0   = blockIdx.x * BN, m0 = blockIdx.y * BM, sid = blockIdx.z;
    int arow = tid >> 1;                // m index 0..127
    int ac4  = (tid & 1) * 4;
    int bkr  = tid >> 5;                // k index 0..7 for B loads
    int bnc  = (tid & 31) * 4;          // n offset 0..124
    int tx   = tid & 15, ty = tid >> 4;

    const int KT_TOT = Rc / BK;         // 1250
    const int PER    = (KT_TOT + NSPLIT - 1) / NSPLIT;  // 79
    int kt0 = sid * PER;
    int kt1 = min(KT_TOT, kt0 + PER);

    float fa[4]; float4 pb;
    auto fetch = [&](int kt, float* a4, float4& b4) {
        int k0 = kt * BK;
        const float* ap = &g_sf[(m0 + arow) * RP1 + k0 + ac4];
        a4[0] = ap[0]; a4[1] = ap[1]; a4[2] = ap[2]; a4[3] = ap[3];
        b4 = *(const float4*)&emb_w[(k0 + bkr) * Ec + n0 + bnc];
    };

    float acc[8][8] = {};
    int buf = 0;
    if (kt0 < kt1) {
        fetch(kt0, fa, pb);
        As[0][ac4 + 0][arow] = fa[0]; As[0][ac4 + 1][arow] = fa[1];
        As[0][ac4 + 2][arow] = fa[2]; As[0][ac4 + 3][arow] = fa[3];
        *(float4*)&Bs[0][bkr][bnc] = pb;
    }
    __syncthreads();

    for (int kt = kt0; kt < kt1; kt++) {
        if (kt + 1 < kt1) fetch(kt + 1, fa, pb);
        #pragma unroll
        for (int kk = 0; kk < BK; kk++) {
            float a[8], b[8];
            *(float4*)&a[0] = *(const float4*)&As[buf][kk][ty * 8];
            *(float4*)&a[4] = *(const float4*)&As[buf][kk][ty * 8 + 4];
            *(float4*)&b[0] = *(const float4*)&Bs[buf][kk][tx * 8];
            *(float4*)&b[4] = *(const float4*)&Bs[buf][kk][tx * 8 + 4];
            #pragma unroll
            for (int i = 0; i < 8; i++)
                #pragma unroll
                for (int j = 0; j < 8; j++)
                    acc[i][j] = fmaf(a[i], b[j], acc[i][j]);
        }
        if (kt + 1 < kt1) {
            int nb = buf ^ 1;
            As[nb][ac4 + 0][arow] = fa[0]; As[nb][ac4 + 1][arow] = fa[1];
            As[nb][ac4 + 2][arow] = fa[2]; As[nb][ac4 + 3][arow] = fa[3];
            *(float4*)&Bs[nb][bkr][bnc] = pb;
        }
        __syncthreads();
        buf ^= 1;
    }

    float* P = &g_part[sid * (Bc * Ec)];
    #pragma unroll
    for (int i = 0; i < 8; i++)
        #pragma unroll
        for (int j = 0; j < 8; j++)
            P[(m0 + ty * 8 + i) * Ec + n0 + tx * 8 + j] = acc[i][j];
}

// ---------------- fc1: 64x64x16 NT GEMM (small: M=1024,N=256,K=512) -------------
// C = relu(g_ec @ fc1_w^T + fc1_b) -> g_h1
__global__ void __launch_bounds__(256)
k_fc1(const float* __restrict__ W, const float* __restrict__ bias)
{
    __shared__ float As[16][64];
    __shared__ float Bs[16][64];

    int tid = threadIdx.x;
    int tx = tid & 15, ty = tid >> 4;
    int m0 = blockIdx.y * 64, n0 = blockIdx.x * 64;

    int lm = tid >> 2;
    int lk = (tid & 3) * 4;

    float acc[4][4] = {};

    for (int k0 = 0; k0 < ECC; k0 += 16) {
        float4 av = *(const float4*)&g_ec[(m0 + lm) * ECC + k0 + lk];
        As[lk + 0][lm] = av.x; As[lk + 1][lm] = av.y;
        As[lk + 2][lm] = av.z; As[lk + 3][lm] = av.w;
        float4 bv = *(const float4*)&W[(n0 + lm) * ECC + k0 + lk];
        Bs[lk + 0][lm] = bv.x; Bs[lk + 1][lm] = bv.y;
        Bs[lk + 2][lm] = bv.z; Bs[lk + 3][lm] = bv.w;
        __syncthreads();

        #pragma unroll
        for (int kk = 0; kk < 16; kk++) {
            float a[4], b[4];
            *(float4*)a = *(const float4*)&As[kk][ty * 4];
            *(float4*)b = *(const float4*)&Bs[kk][tx * 4];
            #pragma unroll
            for (int i = 0; i < 4; i++)
                #pragma unroll
                for (int j = 0; j < 4; j++)
                    acc[i][j] = fmaf(a[i], b[j], acc[i][j]);
        }
        __syncthreads();
    }

    #pragma unroll
    for (int i = 0; i < 4; i++) {
        int m = m0 + ty * 4 + i;
        #pragma unroll
        for (int j = 0; j < 4; j++) {
            int n = n0 + tx * 4 + j;
            g_h1[m * Ec + n] = fmaxf(acc[i][j] + bias[n], 0.f);
        }
    }
}

// ---------------- softmax over RP1 per row (block/row, smem-cached) ----------
__global__ void __launch_bounds__(256)
k_softmax(const float* __restrict__ in)
{
    __shared__ float buf[RP1];
    __shared__ float red[256];
    int row = blockIdx.x, tid = threadIdx.x;
    const float* x = in + row * RP1;

    float mx = -1e30f;
    for (int j = tid; j < RP1; j += 256) {
        float v = x[j];
        buf[j] = v;
        mx = fmaxf(mx, v);
    }
    red[tid] = mx;
    __syncthreads();
    for (int s = 128; s > 0; s >>= 1) {
        if (tid < s) red[tid] = fmaxf(red[tid], red[tid + s]);
        __syncthreads();
    }
    mx = red[0];
    __syncthreads();

    float sm = 0.f;
    for (int j = tid; j < RP1; j += 256) {
        float e = __expf(buf[j] - mx);
        buf[j] = e;
        sm += e;
    }
    red[tid] = sm;
    __syncthreads();
    for (int s = 128; s > 0; s >>= 1) {
        if (tid < s) red[tid] += red[tid + s];
        __syncthreads();
    }
    float inv = 1.f / red[0];
    for (int j = tid; j < RP1; j += 256)
        g_sf[row * RP1 + j] = buf[j] * inv;
}

// ---------------- launch sequence ----------------
extern "C" void kernel_launch(void* const* d_in, const int* in_sizes, int n_in,
                              void* d_out, int out_size)
{
    const int*   bodys = (const int*)  d_in[0];
    const float* emb_w = (const float*)d_in[1];
    const float* w_ih  = (const float*)d_in[2];
    const float* w_hh  = (const float*)d_in[3];
    const float* b_ih  = (const float*)d_in[4];
    const float* b_hh  = (const float*)d_in[5];
    const float* fc1_w = (const float*)d_in[6];
    const float* fc1_b = (const float*)d_in[7];
    const float* fc2_w = (const float*)d_in[8];
    const float* fc2_b = (const float*)d_in[9];
    float* out = (float*)d_out;

    // Embed + init
    k_embed<<<(Bc * Lc * Ec) / 256, 256>>>(bodys, emb_w);
    k_init<<<(Bc * Ec) / 256, 256>>>(b_ih, b_hh);

    // LSTM: steps 0..6 only (step 7's hidden state is never consumed)
    for (int t = 0; t < Lc - 1; t++) {
        k_gates<<<dim3(G4 / BN, Bc / BM), 256>>>(t, w_ih, w_hh);
        k_lstm_point<<<(Bc * Ec) / 256, 256>>>(t);
    }

    // Autoregressive loop
    for (int i = 0; i < Lc - 1; i++) {
        if (i == 0) {
            k_ec0<<<(Bc * Ec) / 256, 256>>>();
        } else {
            k_nn<<<dim3(Ec / BN, Bc / BM, NSPLIT), 256>>>(emb_w);
            k_nn_reduce<<<(Bc * Ec) / 256, 256>>>(i);
            k_ec_second<<<(Bc * Ec) / 256, 256>>>(emb_w, i);
        }
        // fc1: (B,512)@(512->256), relu+bias
        k_fc1<<<dim3(Ec / 64, Bc / 64), 256>>>(fc1_w, fc1_b);
        // fc2: (B,256)@(256->10001), bias, write directly into d_out (final iter persists)
        k_fc2<<<dim3((RP1 + BN - 1) / BN, Bc / BM), 256>>>(fc2_w, fc2_b, out);
        // softmax feeds the NEXT iteration; skip on the last one
        if (i < Lc - 2) k_softmax<<<Bc, 256>>>(out);
    }

    // emb_concat (final) appended after prob in d_out
    k_copy_ec<<<(Bc * ECC) / 256, 256>>>(out, out_size);
}